// round 1
// baseline (speedup 1.0000x reference)
#include <cuda_runtime.h>
#include <stdint.h>

// ---------------- scratch (static __device__, no allocs) ----------------
__device__ float    g_partial[64];
__device__ float    g_alpha2[4];                 // a1^2, a2^2, a3^2, af^2
__device__ unsigned g_w1b[64];                   // 27 bits: c*9 + kh*3 + kw
__device__ unsigned g_w2b[128 * 18];             // [o][t][j]  j: ch word (64ch -> 2)
__device__ unsigned g_w3b[256 * 36];             // [o][t][j]  j: ch word (128ch -> 4)
__device__ __align__(16) unsigned g_wfb[1000 * 8]; // [k][j] 256 bits
__device__ uint2    g_a1b[32 * 112 * 112];       // layer1 sign bits, 64 ch
__device__ uint4    g_a2b[32 * 56 * 56];         // layer2 sign bits, 128 ch
__device__ __align__(16) unsigned g_pb[32 * 8];  // pooled sign bits, 256 ch

// ---------------- alpha = mean(|w|), two-stage deterministic ----------------
__global__ void k_abs_partial(const float* __restrict__ w1, const float* __restrict__ w2,
                              const float* __restrict__ w3, const float* __restrict__ wf) {
    int t = blockIdx.x >> 4, j = blockIdx.x & 15;
    const float* p; int N;
    if      (t == 0) { p = w1; N = 1728;   }
    else if (t == 1) { p = w2; N = 73728;  }
    else if (t == 2) { p = w3; N = 294912; }
    else             { p = wf; N = 256000; }
    float s = 0.f;
    for (int i = j * 256 + threadIdx.x; i < N; i += 16 * 256) s += fabsf(p[i]);
    __shared__ float sh[256];
    sh[threadIdx.x] = s; __syncthreads();
    for (int k = 128; k > 0; k >>= 1) {
        if (threadIdx.x < k) sh[threadIdx.x] += sh[threadIdx.x + k];
        __syncthreads();
    }
    if (threadIdx.x == 0) g_partial[blockIdx.x] = sh[0];
}

__global__ void k_alpha_final() {
    int t = threadIdx.x;
    if (t >= 4) return;
    const int Ns[4] = {1728, 73728, 294912, 256000};
    float s = 0.f;
    for (int j = 0; j < 16; j++) s += g_partial[t * 16 + j];
    float a = s / (float)Ns[t];
    g_alpha2[t] = a * a;
}

// ---------------- weight bit packing (bit=1 <=> w < 0) ----------------
__global__ void k_pack1(const float* __restrict__ w1) {
    int o = threadIdx.x;                    // 64 threads
    unsigned b = 0;
    for (int t = 0; t < 27; t++) if (w1[o * 27 + t] < 0.f) b |= 1u << t;
    g_w1b[o] = b;
}
__global__ void k_pack2(const float* __restrict__ w2) {
    int id = blockIdx.x * blockDim.x + threadIdx.x;
    if (id >= 128 * 18) return;
    int o = id / 18, r = id % 18, t = r >> 1, j = r & 1;
    unsigned b = 0;
    for (int c = 0; c < 32; c++)
        if (w2[o * 576 + (j * 32 + c) * 9 + t] < 0.f) b |= 1u << c;
    g_w2b[o * 18 + t * 2 + j] = b;
}
__global__ void k_pack3(const float* __restrict__ w3) {
    int id = blockIdx.x * blockDim.x + threadIdx.x;
    if (id >= 256 * 36) return;
    int o = id / 36, r = id % 36, t = r >> 2, j = r & 3;
    unsigned b = 0;
    for (int c = 0; c < 32; c++)
        if (w3[o * 1152 + (j * 32 + c) * 9 + t] < 0.f) b |= 1u << c;
    g_w3b[o * 36 + t * 4 + j] = b;
}
__global__ void k_packf(const float* __restrict__ wf) {
    int id = blockIdx.x * blockDim.x + threadIdx.x;
    if (id >= 1000 * 8) return;
    int k = id / 8, j = id % 8;
    unsigned b = 0;
    for (int c = 0; c < 32; c++)
        if (wf[k * 256 + j * 32 + c] < 0.f) b |= 1u << c;
    g_wfb[k * 8 + j] = b;
}

// ---------------- layer 1: x[32,3,224,224] -> sign bits [32,112,112] x 64ch ----------------
__global__ void __launch_bounds__(128) k_conv1(const float* __restrict__ x,
                                               const float* __restrict__ b1) {
    __shared__ unsigned sw[64];
    __shared__ float    sb[64];
    if (threadIdx.x < 64) { sw[threadIdx.x] = g_w1b[threadIdx.x]; sb[threadIdx.x] = b1[threadIdx.x]; }
    __syncthreads();

    int idx = blockIdx.x * 128 + threadIdx.x;      // 401408 total, exact
    int n = idx / 12544, r = idx % 12544;
    int oh = r / 112, ow = r % 112;
    float a1sq = g_alpha2[0];

    unsigned xb = 0, mask = 0;
    const float* xp = x + (size_t)n * (3 * 224 * 224);
    #pragma unroll
    for (int kh = 0; kh < 3; kh++) {
        int ih = 2 * oh - 1 + kh;
        if ((unsigned)ih >= 224u) continue;
        #pragma unroll
        for (int kw = 0; kw < 3; kw++) {
            int iw = 2 * ow - 1 + kw;
            if ((unsigned)iw >= 224u) continue;
            int t = kh * 3 + kw;
            mask |= 0x40201u << t;                 // bits t, 9+t, 18+t
            int base = ih * 224 + iw;
            if (xp[base]          < 0.f) xb |= 1u << t;
            if (xp[50176 + base]  < 0.f) xb |= 1u << (9 + t);
            if (xp[100352 + base] < 0.f) xb |= 1u << (18 + t);
        }
    }
    int V = __popc(mask);
    unsigned wo0 = 0, wo1 = 0;
    #pragma unroll 4
    for (int o = 0; o < 32; o++) {
        int p = __popc((xb ^ sw[o]) & mask);
        float y = fmaf(a1sq, (float)(V - 2 * p), sb[o]);
        wo0 |= (unsigned)(y < 0.f) << o;
    }
    #pragma unroll 4
    for (int o = 0; o < 32; o++) {
        int p = __popc((xb ^ sw[32 + o]) & mask);
        float y = fmaf(a1sq, (float)(V - 2 * p), sb[32 + o]);
        wo1 |= (unsigned)(y < 0.f) << o;
    }
    g_a1b[idx] = make_uint2(wo0, wo1);
}

// ---------------- layer 2: XNOR conv 64->128, stride 2, 112->56 ----------------
__device__ __forceinline__ int gather2(int n, int oh, int ow, uint2* a, int* tapid) {
    int nv = 0;
    const uint2* src = g_a1b + n * 12544;
    #pragma unroll
    for (int kh = 0; kh < 3; kh++) {
        int ih = 2 * oh - 1 + kh;
        if ((unsigned)ih >= 112u) continue;
        #pragma unroll
        for (int kw = 0; kw < 3; kw++) {
            int iw = 2 * ow - 1 + kw;
            if ((unsigned)iw >= 112u) continue;
            a[nv] = src[ih * 112 + iw];
            tapid[nv] = kh * 3 + kw;
            nv++;
        }
    }
    return nv;
}

__device__ __forceinline__ void conv2_one(const unsigned* sw, const float* sb, float a2sq,
                                          const uint2* a, const int* tapid, int nv, int pix) {
    int V = 64 * nv;
    unsigned words[4];
    #pragma unroll
    for (int j = 0; j < 4; j++) {
        unsigned w = 0;
        #pragma unroll 1
        for (int oo = 0; oo < 32; oo++) {
            int o = j * 32 + oo;
            int P = 0;
            for (int t = 0; t < nv; t++) {
                const unsigned* wp = &sw[o * 18 + tapid[t] * 2];
                P += __popc(a[t].x ^ wp[0]) + __popc(a[t].y ^ wp[1]);
            }
            float y = fmaf(a2sq, (float)(V - 2 * P), sb[o]);
            w |= (unsigned)(y < 0.f) << oo;
        }
        words[j] = w;
    }
    g_a2b[pix] = make_uint4(words[0], words[1], words[2], words[3]);
}

__global__ void __launch_bounds__(128) k_conv2(const float* __restrict__ b2) {
    __shared__ unsigned sw[2304];
    __shared__ float    sb[128];
    for (int i = threadIdx.x; i < 2304; i += 128) sw[i] = g_w2b[i];
    if (threadIdx.x < 128) sb[threadIdx.x] = b2[threadIdx.x];
    __syncthreads();

    float a2sq = g_alpha2[1];
    int tid = blockIdx.x * 128 + threadIdx.x;      // 50176 threads, 2 pixels each
    int p0 = tid * 2, p1 = p0 + 1;                 // same row always (56 even)
    int n = p0 / 3136, r = p0 % 3136;
    int oh = r / 56, ow0 = r % 56, ow1 = ow0 + 1;

    uint2 a0[9], a1[9]; int t0[9], t1[9];
    int nv0 = gather2(n, oh, ow0, a0, t0);
    int nv1 = gather2(n, oh, ow1, a1, t1);

    if (nv0 == 9 && nv1 == 9) {                    // interior fast path
        unsigned r0[4], r1[4];
        #pragma unroll
        for (int j = 0; j < 4; j++) {
            unsigned w0 = 0, w1 = 0;
            #pragma unroll 1
            for (int oo = 0; oo < 32; oo++) {
                int o = j * 32 + oo;
                const unsigned* wp = &sw[o * 18];
                int P0 = 0, P1 = 0;
                #pragma unroll
                for (int t = 0; t < 9; t++) {
                    unsigned ww0 = wp[t * 2], ww1 = wp[t * 2 + 1];
                    P0 += __popc(a0[t].x ^ ww0) + __popc(a0[t].y ^ ww1);
                    P1 += __popc(a1[t].x ^ ww0) + __popc(a1[t].y ^ ww1);
                }
                float y0 = fmaf(a2sq, (float)(576 - 2 * P0), sb[o]);
                float y1 = fmaf(a2sq, (float)(576 - 2 * P1), sb[o]);
                w0 |= (unsigned)(y0 < 0.f) << oo;
                w1 |= (unsigned)(y1 < 0.f) << oo;
            }
            r0[j] = w0; r1[j] = w1;
        }
        g_a2b[p0] = make_uint4(r0[0], r0[1], r0[2], r0[3]);
        g_a2b[p1] = make_uint4(r1[0], r1[1], r1[2], r1[3]);
    } else {
        conv2_one(sw, sb, a2sq, a0, t0, nv0, p0);
        conv2_one(sw, sb, a2sq, a1, t1, nv1, p1);
    }
}

// ---------------- layer 3: XNOR conv 128->256, 56->28, fused global-avg-pool sign ----------------
__global__ void __launch_bounds__(256) k_conv3(const float* __restrict__ b3) {
    int n = blockIdx.x >> 3, cg = blockIdx.x & 7;  // 32 channels per block
    __shared__ unsigned sw[1152];
    __shared__ float    sb[32];
    __shared__ int      ssum[32];
    __shared__ float    scorr[32];
    for (int i = threadIdx.x; i < 1152; i += 256) sw[i] = g_w3b[cg * 1152 + i];
    if (threadIdx.x < 32) {
        sb[threadIdx.x] = b3[cg * 32 + threadIdx.x];
        ssum[threadIdx.x] = 0;
        scorr[threadIdx.x] = 0.f;
    }
    __syncthreads();

    float a3sq = g_alpha2[2];
    int acc[32];
    #pragma unroll
    for (int c = 0; c < 32; c++) acc[c] = 0;

    for (int pix = threadIdx.x; pix < 784; pix += 256) {
        int oh = pix / 28, ow = pix % 28;
        uint4 a[9]; int tapid[9]; int nv = 0;
        const uint4* src = g_a2b + n * 3136;
        #pragma unroll
        for (int kh = 0; kh < 3; kh++) {
            int ih = 2 * oh - 1 + kh;
            if ((unsigned)ih >= 56u) continue;
            #pragma unroll
            for (int kw = 0; kw < 3; kw++) {
                int iw = 2 * ow - 1 + kw;
                if ((unsigned)iw >= 56u) continue;
                a[nv] = src[ih * 56 + iw];
                tapid[nv] = kh * 3 + kw;
                nv++;
            }
        }
        if (nv == 9) {
            #pragma unroll
            for (int c = 0; c < 32; c++) {
                const unsigned* wp = &sw[c * 36];
                int P = 0;
                #pragma unroll 3
                for (int t = 0; t < 9; t++) {
                    P += __popc(a[t].x ^ wp[t * 4 + 0]) + __popc(a[t].y ^ wp[t * 4 + 1])
                       + __popc(a[t].z ^ wp[t * 4 + 2]) + __popc(a[t].w ^ wp[t * 4 + 3]);
                }
                int I = 1152 - 2 * P;
                float y = fmaf(a3sq, (float)I, sb[c]);
                if (y > 1.f)       atomicAdd(&scorr[c],  1.f - y);
                else if (y < -1.f) atomicAdd(&scorr[c], -1.f - y);
                acc[c] += I;
            }
        } else {
            int V = 128 * nv;
            #pragma unroll
            for (int c = 0; c < 32; c++) {
                int P = 0;
                for (int t = 0; t < nv; t++) {
                    const unsigned* wp = &sw[c * 36 + tapid[t] * 4];
                    P += __popc(a[t].x ^ wp[0]) + __popc(a[t].y ^ wp[1])
                       + __popc(a[t].z ^ wp[2]) + __popc(a[t].w ^ wp[3]);
                }
                int I = V - 2 * P;
                float y = fmaf(a3sq, (float)I, sb[c]);
                if (y > 1.f)       atomicAdd(&scorr[c],  1.f - y);
                else if (y < -1.f) atomicAdd(&scorr[c], -1.f - y);
                acc[c] += I;
            }
        }
    }

    // block reduction: warp shuffle then shared int atomics (exact, deterministic)
    #pragma unroll
    for (int c = 0; c < 32; c++) {
        int v = acc[c];
        #pragma unroll
        for (int s = 16; s > 0; s >>= 1) v += __shfl_xor_sync(0xffffffffu, v, s);
        if ((threadIdx.x & 31) == 0) atomicAdd(&ssum[c], v);
    }
    __syncthreads();

    if (threadIdx.x < 32) {
        int c = threadIdx.x;
        // sum of clipped values over 784 pixels = a3sq*sum(I) + 784*b3 + clip corrections
        float val = fmaf(a3sq, (float)ssum[c], 784.f * sb[c] + scorr[c]);
        unsigned bits = __ballot_sync(0xffffffffu, val < 0.f);
        if (c == 0) g_pb[n * 8 + cg] = bits;
    }
}

// ---------------- FC: out[n,k] = af^2 * (256 - 2P) + bf[k] ----------------
__global__ void k_fc(const float* __restrict__ bf, float* __restrict__ out) {
    int idx = blockIdx.x * 128 + threadIdx.x;
    if (idx >= 32000) return;
    int n = idx / 1000, k = idx % 1000;
    float afsq = g_alpha2[3];
    const uint4* pb = (const uint4*)(g_pb + n * 8);
    const uint4* wb = (const uint4*)(g_wfb + k * 8);
    uint4 p0 = pb[0], p1 = pb[1], w0 = wb[0], w1 = wb[1];
    int P = __popc(p0.x ^ w0.x) + __popc(p0.y ^ w0.y) + __popc(p0.z ^ w0.z) + __popc(p0.w ^ w0.w)
          + __popc(p1.x ^ w1.x) + __popc(p1.y ^ w1.y) + __popc(p1.z ^ w1.z) + __popc(p1.w ^ w1.w);
    out[idx] = fmaf(afsq, (float)(256 - 2 * P), bf[k]);
}

// ---------------- launch ----------------
extern "C" void kernel_launch(void* const* d_in, const int* in_sizes, int n_in,
                              void* d_out, int out_size) {
    const float* x  = (const float*)d_in[0];
    const float* w1 = (const float*)d_in[1];
    const float* b1 = (const float*)d_in[2];
    const float* w2 = (const float*)d_in[3];
    const float* b2 = (const float*)d_in[4];
    const float* w3 = (const float*)d_in[5];
    const float* b3 = (const float*)d_in[6];
    const float* wf = (const float*)d_in[7];
    const float* bf = (const float*)d_in[8];
    float* out = (float*)d_out;

    k_abs_partial<<<64, 256>>>(w1, w2, w3, wf);
    k_alpha_final<<<1, 32>>>();
    k_pack1<<<1, 64>>>(w1);
    k_pack2<<<18, 128>>>(w2);
    k_pack3<<<72, 128>>>(w3);
    k_packf<<<63, 128>>>(wf);
    k_conv1<<<3136, 128>>>(x, b1);
    k_conv2<<<392, 128>>>(b2);
    k_conv3<<<256, 256>>>(b3);
    k_fc<<<250, 128>>>(bf, out);
}

// round 2
// speedup vs baseline: 1.5426x; 1.5426x over previous
#include <cuda_runtime.h>
#include <stdint.h>

// ---------------- scratch (static __device__, no allocs) ----------------
__device__ float    g_partial[64];
__device__ float    g_alpha2[4];                   // a1^2, a2^2, a3^2, af^2
__device__ unsigned g_w1b[64];                     // 27 bits: c*9 + kh*3 + kw
__device__ unsigned g_w2b[128 * 18];               // [o][t][j]  j: ch word (64ch -> 2)
__device__ unsigned g_w3b[256 * 36];               // [o][t][j]  j: ch word (128ch -> 4)
__device__ __align__(16) unsigned g_wfb[1000 * 8]; // [k][j] 256 bits
__device__ uint2    g_a1b[32 * 112 * 112];         // layer1 sign bits, 64 ch
__device__ uint4    g_a2b[32 * 56 * 56];           // layer2 sign bits, 128 ch
__device__ __align__(16) unsigned char g_pb[32 * 32]; // pooled sign bits, byte = 8 ch

// ---------------- prep: alpha partials + all weight bit-packing, one launch ----------------
__global__ void __launch_bounds__(256) k_prep(const float* __restrict__ w1,
                                              const float* __restrict__ w2,
                                              const float* __restrict__ w3,
                                              const float* __restrict__ wf) {
    int b = blockIdx.x, tid = threadIdx.x;
    if (b < 64) {                                   // abs-sum partials
        int t = b >> 4, j = b & 15;
        const float* p; int N;
        if      (t == 0) { p = w1; N = 1728;   }
        else if (t == 1) { p = w2; N = 73728;  }
        else if (t == 2) { p = w3; N = 294912; }
        else             { p = wf; N = 256000; }
        float s = 0.f;
        for (int i = j * 256 + tid; i < N; i += 16 * 256) s += fabsf(p[i]);
        __shared__ float sh[256];
        sh[tid] = s; __syncthreads();
        for (int k = 128; k > 0; k >>= 1) {
            if (tid < k) sh[tid] += sh[tid + k];
            __syncthreads();
        }
        if (tid == 0) g_partial[b] = sh[0];
    } else if (b == 64) {                           // pack w1
        if (tid < 64) {
            int o = tid;
            unsigned bb = 0;
            for (int t = 0; t < 27; t++) if (w1[o * 27 + t] < 0.f) bb |= 1u << t;
            g_w1b[o] = bb;
        }
    } else if (b < 74) {                            // pack w2: 2304 ids
        int id = (b - 65) * 256 + tid;
        if (id < 128 * 18) {
            int o = id / 18, r = id % 18, t = r >> 1, j = r & 1;
            unsigned bb = 0;
            for (int c = 0; c < 32; c++)
                if (w2[o * 576 + (j * 32 + c) * 9 + t] < 0.f) bb |= 1u << c;
            g_w2b[o * 18 + t * 2 + j] = bb;
        }
    } else if (b < 110) {                           // pack w3: 9216 ids
        int id = (b - 74) * 256 + tid;
        if (id < 256 * 36) {
            int o = id / 36, r = id % 36, t = r >> 2, j = r & 3;
            unsigned bb = 0;
            for (int c = 0; c < 32; c++)
                if (w3[o * 1152 + (j * 32 + c) * 9 + t] < 0.f) bb |= 1u << c;
            g_w3b[o * 36 + t * 4 + j] = bb;
        }
    } else {                                        // pack wf: 8000 ids
        int id = (b - 110) * 256 + tid;
        if (id < 1000 * 8) {
            int k = id / 8, j = id % 8;
            unsigned bb = 0;
            for (int c = 0; c < 32; c++)
                if (wf[k * 256 + j * 32 + c] < 0.f) bb |= 1u << c;
            g_wfb[k * 8 + j] = bb;
        }
    }
}

__global__ void k_alpha_final() {
    int t = threadIdx.x;
    if (t >= 4) return;
    const int Ns[4] = {1728, 73728, 294912, 256000};
    float s = 0.f;
    for (int j = 0; j < 16; j++) s += g_partial[t * 16 + j];
    float a = s / (float)Ns[t];
    g_alpha2[t] = a * a;
}

// ---------------- layer 1: x[32,3,224,224] -> sign bits [32,112,112] x 64ch ----------------
__global__ void __launch_bounds__(128) k_conv1(const float* __restrict__ x,
                                               const float* __restrict__ b1) {
    __shared__ unsigned sw[64];
    __shared__ float    sb[64];
    if (threadIdx.x < 64) { sw[threadIdx.x] = g_w1b[threadIdx.x]; sb[threadIdx.x] = b1[threadIdx.x]; }
    __syncthreads();

    int idx = blockIdx.x * 128 + threadIdx.x;       // 401408 total, exact
    int n = idx / 12544, r = idx % 12544;
    int oh = r / 112, ow = r % 112;
    float a1sq = g_alpha2[0];
    const float* xp = x + (size_t)n * 150528;

    unsigned xb = 0, mask;
    int V;
    if (oh > 0 && ow > 0) {                         // interior: all 9 taps valid
        int base = (2 * oh - 1) * 224 + (2 * ow - 1);
        #pragma unroll
        for (int ch = 0; ch < 3; ch++)
            #pragma unroll
            for (int t = 0; t < 9; t++) {
                float v = xp[ch * 50176 + base + (t / 3) * 224 + (t % 3)];
                xb |= (unsigned)(v < 0.f) << (ch * 9 + t);
            }
        V = 27; mask = 0x7FFFFFFu;
    } else {
        mask = 0;
        #pragma unroll
        for (int kh = 0; kh < 3; kh++) {
            int ih = 2 * oh - 1 + kh;
            if ((unsigned)ih >= 224u) continue;
            #pragma unroll
            for (int kw = 0; kw < 3; kw++) {
                int iw = 2 * ow - 1 + kw;
                if ((unsigned)iw >= 224u) continue;
                int t = kh * 3 + kw;
                mask |= 0x40201u << t;              // bits t, 9+t, 18+t
                int base = ih * 224 + iw;
                if (xp[base]          < 0.f) xb |= 1u << t;
                if (xp[50176 + base]  < 0.f) xb |= 1u << (9 + t);
                if (xp[100352 + base] < 0.f) xb |= 1u << (18 + t);
            }
        }
        V = __popc(mask);
    }

    unsigned wo0 = 0, wo1 = 0;
    #pragma unroll 4
    for (int o = 0; o < 32; o++) {
        int p = __popc((xb ^ sw[o]) & mask);
        float y = fmaf(a1sq, (float)(V - 2 * p), sb[o]);
        wo0 |= (unsigned)(y < 0.f) << o;
    }
    #pragma unroll 4
    for (int o = 0; o < 32; o++) {
        int p = __popc((xb ^ sw[32 + o]) & mask);
        float y = fmaf(a1sq, (float)(V - 2 * p), sb[32 + o]);
        wo1 |= (unsigned)(y < 0.f) << o;
    }
    g_a1b[idx] = make_uint2(wo0, wo1);
}

// ---------------- layer 2: XNOR conv 64->128, stride 2, 112->56 ----------------
__device__ __noinline__ void conv2_slow(const uint2* __restrict__ src,
                                        const unsigned* sw, const float* sb,
                                        float a2sq, int oh, int ow, int pix,
                                        unsigned* __restrict__ outp) {
    uint2 a[9]; int f[9];
    #pragma unroll
    for (int kh = 0; kh < 3; kh++)
        #pragma unroll
        for (int kw = 0; kw < 3; kw++) {
            int t = kh * 3 + kw;
            int ih = 2 * oh - 1 + kh, iw = 2 * ow - 1 + kw;
            bool v = ((unsigned)ih < 112u) && ((unsigned)iw < 112u);
            a[t] = v ? src[ih * 112 + iw] : make_uint2(0u, 0u);
            f[t] = v ? 1 : 0;
        }
    int V = 64 * (f[0] + f[1] + f[2] + f[3] + f[4] + f[5] + f[6] + f[7] + f[8]);
    unsigned wv = 0;
    for (int o = 0; o < 128; o++) {
        const unsigned* wp = &sw[o * 18];
        int P = 0;
        #pragma unroll
        for (int t = 0; t < 9; t++) {
            int d = __popc(a[t].x ^ wp[t * 2]) + __popc(a[t].y ^ wp[t * 2 + 1]);
            P += f[t] * d;
        }
        float y = fmaf(a2sq, (float)(V - 2 * P), sb[o]);
        int oo = o & 31;
        wv |= (unsigned)(y < 0.f) << oo;
        if (oo == 31) { outp[pix * 4 + (o >> 5)] = wv; wv = 0; }
    }
}

__global__ void __launch_bounds__(128) k_conv2(const float* __restrict__ b2) {
    __shared__ unsigned sw[2304];
    __shared__ float    sb[128];
    for (int i = threadIdx.x; i < 2304; i += 128) sw[i] = g_w2b[i];
    if (threadIdx.x < 128) sb[threadIdx.x] = b2[threadIdx.x];
    __syncthreads();

    float a2sq = g_alpha2[1];
    int tid = blockIdx.x * 128 + threadIdx.x;       // 50176 threads, 2 px each
    int q = tid * 2;
    int n = q / 3136, r = q % 3136;
    int oh = r / 56, ow0 = r % 56;                  // ow0 even
    const uint2* src = g_a1b + n * 12544;
    unsigned* outp = (unsigned*)g_a2b;

    if (oh > 0 && ow0 > 0) {                        // interior fast path, static regs
        uint2 c[15];                                // 3 rows x 5 cols window
        int base = (2 * oh - 1) * 112 + (2 * ow0 - 1);
        #pragma unroll
        for (int rr = 0; rr < 3; rr++)
            #pragma unroll
            for (int k = 0; k < 5; k++) c[rr * 5 + k] = src[base + rr * 112 + k];

        unsigned w0v = 0, w1v = 0;
        #pragma unroll 2
        for (int o = 0; o < 128; o++) {
            const unsigned* wp = &sw[o * 18];
            int P0 = 0, P1 = 0;
            #pragma unroll
            for (int rr = 0; rr < 3; rr++)
                #pragma unroll
                for (int kw = 0; kw < 3; kw++) {
                    unsigned ww0 = wp[(rr * 3 + kw) * 2], ww1 = wp[(rr * 3 + kw) * 2 + 1];
                    uint2 l = c[rr * 5 + kw], rt = c[rr * 5 + kw + 2];
                    P0 += __popc(l.x ^ ww0) + __popc(l.y ^ ww1);
                    P1 += __popc(rt.x ^ ww0) + __popc(rt.y ^ ww1);
                }
            float y0 = fmaf(a2sq, (float)(576 - 2 * P0), sb[o]);
            float y1 = fmaf(a2sq, (float)(576 - 2 * P1), sb[o]);
            int oo = o & 31;
            w0v |= (unsigned)(y0 < 0.f) << oo;
            w1v |= (unsigned)(y1 < 0.f) << oo;
            if (oo == 31) {
                outp[q * 4 + (o >> 5)] = w0v;
                outp[(q + 1) * 4 + (o >> 5)] = w1v;
                w0v = 0; w1v = 0;
            }
        }
    } else {
        conv2_slow(src, sw, sb, a2sq, oh, ow0,     q,     outp);
        conv2_slow(src, sw, sb, a2sq, oh, ow0 + 1, q + 1, outp);
    }
}

// ---------------- layer 3: XNOR conv 128->256, 56->28, fused global-avg-pool sign ----------------
__global__ void __launch_bounds__(256) k_conv3(const float* __restrict__ b3) {
    int n = blockIdx.x >> 5, g = blockIdx.x & 31;   // octet g: channels g*8..g*8+7
    __shared__ unsigned sw[288];
    __shared__ float    sb[8];
    __shared__ int      ssum[8];
    __shared__ float    scorr[8];
    for (int i = threadIdx.x; i < 288; i += 256) sw[i] = g_w3b[g * 288 + i];
    if (threadIdx.x < 8) {
        sb[threadIdx.x] = b3[g * 8 + threadIdx.x];
        ssum[threadIdx.x] = 0;
        scorr[threadIdx.x] = 0.f;
    }
    __syncthreads();

    float a3sq = g_alpha2[2];
    int acc[8];
    #pragma unroll
    for (int c = 0; c < 8; c++) acc[c] = 0;
    const uint4* src = g_a2b + n * 3136;

    for (int pix = threadIdx.x; pix < 784; pix += 256) {
        int oh = pix / 28, ow = pix % 28;
        if (oh > 0 && ow > 0) {                     // interior fast path
            uint4 a[9];
            int base = (2 * oh - 1) * 56 + (2 * ow - 1);
            #pragma unroll
            for (int rr = 0; rr < 3; rr++)
                #pragma unroll
                for (int kw = 0; kw < 3; kw++) a[rr * 3 + kw] = src[base + rr * 56 + kw];
            #pragma unroll
            for (int c = 0; c < 8; c++) {
                const unsigned* wp = &sw[c * 36];
                int P = 0;
                #pragma unroll
                for (int t = 0; t < 9; t++) {
                    uint4 av = a[t];
                    P += __popc(av.x ^ wp[t * 4 + 0]) + __popc(av.y ^ wp[t * 4 + 1])
                       + __popc(av.z ^ wp[t * 4 + 2]) + __popc(av.w ^ wp[t * 4 + 3]);
                }
                int I = 1152 - 2 * P;
                acc[c] += I;
                float y = fmaf(a3sq, (float)I, sb[c]);
                if (fabsf(y) > 1.f) atomicAdd(&scorr[c], (y > 0.f ? 1.f : -1.f) - y);
            }
        } else {                                    // border: gated, static arrays
            uint4 a[9]; int f[9];
            #pragma unroll
            for (int kh = 0; kh < 3; kh++)
                #pragma unroll
                for (int kw = 0; kw < 3; kw++) {
                    int t = kh * 3 + kw;
                    int ih = 2 * oh - 1 + kh, iw = 2 * ow - 1 + kw;
                    bool v = ((unsigned)ih < 56u) && ((unsigned)iw < 56u);
                    a[t] = v ? src[ih * 56 + iw] : make_uint4(0u, 0u, 0u, 0u);
                    f[t] = v ? 1 : 0;
                }
            int V = 128 * (f[0] + f[1] + f[2] + f[3] + f[4] + f[5] + f[6] + f[7] + f[8]);
            #pragma unroll
            for (int c = 0; c < 8; c++) {
                const unsigned* wp = &sw[c * 36];
                int P = 0;
                #pragma unroll
                for (int t = 0; t < 9; t++) {
                    int d = __popc(a[t].x ^ wp[t * 4 + 0]) + __popc(a[t].y ^ wp[t * 4 + 1])
                          + __popc(a[t].z ^ wp[t * 4 + 2]) + __popc(a[t].w ^ wp[t * 4 + 3]);
                    P += f[t] * d;
                }
                int I = V - 2 * P;
                acc[c] += I;
                float y = fmaf(a3sq, (float)I, sb[c]);
                if (fabsf(y) > 1.f) atomicAdd(&scorr[c], (y > 0.f ? 1.f : -1.f) - y);
            }
        }
    }

    // block reduction: warp shuffle then shared int atomics (exact, deterministic)
    #pragma unroll
    for (int c = 0; c < 8; c++) {
        int v = acc[c];
        #pragma unroll
        for (int s = 16; s > 0; s >>= 1) v += __shfl_xor_sync(0xffffffffu, v, s);
        if ((threadIdx.x & 31) == 0) atomicAdd(&ssum[c], v);
    }
    __syncthreads();

    if (threadIdx.x < 8) {
        int c = threadIdx.x;
        // sum of clipped values over 784 px = a3sq*sum(I) + 784*b3 + clip corrections
        float val = fmaf(a3sq, (float)ssum[c], 784.f * sb[c] + scorr[c]);
        unsigned m = __ballot_sync(0xffu, val < 0.f) & 0xffu;
        if (c == 0) g_pb[n * 32 + g] = (unsigned char)m;
    }
}

// ---------------- FC: out[n,k] = af^2 * (256 - 2P) + bf[k] ----------------
__global__ void k_fc(const float* __restrict__ bf, float* __restrict__ out) {
    int idx = blockIdx.x * 128 + threadIdx.x;
    if (idx >= 32000) return;
    int n = idx / 1000, k = idx % 1000;
    float afsq = g_alpha2[3];
    const uint4* pb = (const uint4*)(g_pb + n * 32);
    const uint4* wb = (const uint4*)(g_wfb + k * 8);
    uint4 p0 = pb[0], p1 = pb[1], w0 = wb[0], w1 = wb[1];
    int P = __popc(p0.x ^ w0.x) + __popc(p0.y ^ w0.y) + __popc(p0.z ^ w0.z) + __popc(p0.w ^ w0.w)
          + __popc(p1.x ^ w1.x) + __popc(p1.y ^ w1.y) + __popc(p1.z ^ w1.z) + __popc(p1.w ^ w1.w);
    out[idx] = fmaf(afsq, (float)(256 - 2 * P), bf[k]);
}

// ---------------- launch ----------------
extern "C" void kernel_launch(void* const* d_in, const int* in_sizes, int n_in,
                              void* d_out, int out_size) {
    const float* x  = (const float*)d_in[0];
    const float* w1 = (const float*)d_in[1];
    const float* b1 = (const float*)d_in[2];
    const float* w2 = (const float*)d_in[3];
    const float* b2 = (const float*)d_in[4];
    const float* w3 = (const float*)d_in[5];
    const float* b3 = (const float*)d_in[6];
    const float* wf = (const float*)d_in[7];
    const float* bf = (const float*)d_in[8];
    float* out = (float*)d_out;

    k_prep<<<142, 256>>>(w1, w2, w3, wf);
    k_alpha_final<<<1, 32>>>();
    k_conv1<<<3136, 128>>>(x, b1);
    k_conv2<<<392, 128>>>(b2);
    k_conv3<<<1024, 256>>>(b3);
    k_fc<<<250, 128>>>(bf, out);
}

// round 3
// speedup vs baseline: 1.8368x; 1.1907x over previous
#include <cuda_runtime.h>
#include <stdint.h>

// ---------------- scratch (static __device__, no allocs) ----------------
__device__ float    g_partial[64];
__device__ unsigned g_w1b[64];                     // 27 bits: c*9 + kh*3 + kw
__device__ unsigned g_w2b[128 * 18];               // reordered: [oo][jout][t][jin]
__device__ unsigned g_w3b[256 * 36];               // [o][t][jw]
__device__ __align__(16) unsigned g_wfb[1000 * 8]; // [k][j] 256 bits
__device__ uint2    g_a1b[32 * 112 * 112];         // layer1 sign bits, 64 ch
__device__ uint4    g_a2b[32 * 56 * 56];           // layer2 sign bits, 128 ch
__device__ __align__(16) unsigned char g_pb[32 * 32]; // pooled sign bits, byte = 8 ch

// alpha^2 for layer t, recomputed deterministically from fixed-order partials
__device__ __forceinline__ float alpha2_of(int t) {
    float s = 0.f;
    #pragma unroll
    for (int j = 0; j < 16; j++) s += g_partial[t * 16 + j];
    const float Ns[4] = {1728.f, 73728.f, 294912.f, 256000.f};
    float a = s / Ns[t];
    return a * a;
}

// ---------------- prep: alpha partials + all weight bit-packing, one launch ----------------
__global__ void __launch_bounds__(256) k_prep(const float* __restrict__ w1,
                                              const float* __restrict__ w2,
                                              const float* __restrict__ w3,
                                              const float* __restrict__ wf) {
    int b = blockIdx.x, tid = threadIdx.x;
    if (b < 64) {                                   // abs-sum partials
        int t = b >> 4, j = b & 15;
        const float* p; int N;
        if      (t == 0) { p = w1; N = 1728;   }
        else if (t == 1) { p = w2; N = 73728;  }
        else if (t == 2) { p = w3; N = 294912; }
        else             { p = wf; N = 256000; }
        float s = 0.f;
        for (int i = j * 256 + tid; i < N; i += 16 * 256) s += fabsf(p[i]);
        __shared__ float sh[256];
        sh[tid] = s; __syncthreads();
        for (int k = 128; k > 0; k >>= 1) {
            if (tid < k) sh[tid] += sh[tid + k];
            __syncthreads();
        }
        if (tid == 0) g_partial[b] = sh[0];
    } else if (b == 64) {                           // pack w1
        if (tid < 64) {
            int o = tid;
            unsigned bb = 0;
            for (int t = 0; t < 27; t++) if (w1[o * 27 + t] < 0.f) bb |= 1u << t;
            g_w1b[o] = bb;
        }
    } else if (b < 74) {                            // pack w2: 2304 ids, reordered dst
        int id = (b - 65) * 256 + tid;
        if (id < 128 * 18) {
            int o = id / 18, r = id % 18, t = r >> 1, j = r & 1;
            unsigned bb = 0;
            for (int c = 0; c < 32; c++)
                if (w2[o * 576 + (j * 32 + c) * 9 + t] < 0.f) bb |= 1u << c;
            // dst layout: [oo][jout][t][jin]  (oo = o&31, jout = o>>5)
            g_w2b[(o & 31) * 72 + (o >> 5) * 18 + t * 2 + j] = bb;
        }
    } else if (b < 110) {                           // pack w3: 9216 ids
        int id = (b - 74) * 256 + tid;
        if (id < 256 * 36) {
            int o = id / 36, r = id % 36, t = r >> 2, j = r & 3;
            unsigned bb = 0;
            for (int c = 0; c < 32; c++)
                if (w3[o * 1152 + (j * 32 + c) * 9 + t] < 0.f) bb |= 1u << c;
            g_w3b[o * 36 + t * 4 + j] = bb;
        }
    } else {                                        // pack wf: 8000 ids
        int id = (b - 110) * 256 + tid;
        if (id < 1000 * 8) {
            int k = id / 8, j = id % 8;
            unsigned bb = 0;
            for (int c = 0; c < 32; c++)
                if (wf[k * 256 + j * 32 + c] < 0.f) bb |= 1u << c;
            g_wfb[k * 8 + j] = bb;
        }
    }
}

// ---------------- layer 1: x[32,3,224,224] -> sign bits [32,112,112] x 64ch ----------------
__global__ void __launch_bounds__(128) k_conv1(const float* __restrict__ x,
                                               const float* __restrict__ b1) {
    __shared__ unsigned sw[64];
    __shared__ float    sb[64];
    __shared__ float    sh_a;
    if (threadIdx.x < 64) { sw[threadIdx.x] = g_w1b[threadIdx.x]; sb[threadIdx.x] = b1[threadIdx.x]; }
    if (threadIdx.x == 0) sh_a = alpha2_of(0);
    __syncthreads();

    int idx = blockIdx.x * 128 + threadIdx.x;       // 401408 total, exact
    int n = idx / 12544, r = idx % 12544;
    int oh = r / 112, ow = r % 112;
    float a1sq = sh_a;
    const float* xp = x + (size_t)n * 150528;

    unsigned xb = 0, mask;
    int V;
    if (oh > 0 && ow > 0) {                         // interior: all 9 taps valid
        int base = (2 * oh - 1) * 224 + (2 * ow - 1);
        #pragma unroll
        for (int ch = 0; ch < 3; ch++)
            #pragma unroll
            for (int t = 0; t < 9; t++) {
                float v = xp[ch * 50176 + base + (t / 3) * 224 + (t % 3)];
                xb |= (unsigned)(v < 0.f) << (ch * 9 + t);
            }
        V = 27; mask = 0x7FFFFFFu;
    } else {
        mask = 0;
        #pragma unroll
        for (int kh = 0; kh < 3; kh++) {
            int ih = 2 * oh - 1 + kh;
            if ((unsigned)ih >= 224u) continue;
            #pragma unroll
            for (int kw = 0; kw < 3; kw++) {
                int iw = 2 * ow - 1 + kw;
                if ((unsigned)iw >= 224u) continue;
                int t = kh * 3 + kw;
                mask |= 0x40201u << t;              // bits t, 9+t, 18+t
                int base = ih * 224 + iw;
                if (xp[base]          < 0.f) xb |= 1u << t;
                if (xp[50176 + base]  < 0.f) xb |= 1u << (9 + t);
                if (xp[100352 + base] < 0.f) xb |= 1u << (18 + t);
            }
        }
        V = __popc(mask);
    }

    unsigned wo0 = 0, wo1 = 0;
    #pragma unroll 4
    for (int o = 0; o < 32; o++) {
        int p = __popc((xb ^ sw[o]) & mask);
        float y = fmaf(a1sq, (float)(V - 2 * p), sb[o]);
        wo0 |= (unsigned)(y < 0.f) << o;
    }
    #pragma unroll 4
    for (int o = 0; o < 32; o++) {
        int p = __popc((xb ^ sw[32 + o]) & mask);
        float y = fmaf(a1sq, (float)(V - 2 * p), sb[32 + o]);
        wo1 |= (unsigned)(y < 0.f) << o;
    }
    g_a1b[idx] = make_uint2(wo0, wo1);
}

// ---------------- layer 2: XNOR conv 64->128, stride 2, 112->56 ----------------
// thread = (pixel-pair q, output-channel word jout). 200704 threads.
__global__ void __launch_bounds__(128) k_conv2(const float* __restrict__ b2) {
    __shared__ unsigned sw[2304];                   // [oo][jout][t][jin]
    __shared__ float    sb[128];                    // [oo][jout]
    __shared__ float    sh_a;
    for (int i = threadIdx.x; i < 2304; i += 128) sw[i] = g_w2b[i];
    if (threadIdx.x < 128) sb[(threadIdx.x & 31) * 4 + (threadIdx.x >> 5)] = b2[threadIdx.x];
    if (threadIdx.x == 0) sh_a = alpha2_of(1);
    __syncthreads();
    float a2sq = sh_a;

    int t = blockIdx.x * 128 + threadIdx.x;         // 200704 exact
    int jout = t & 3, q = t >> 2;                   // q in [0, 50176)
    int n = q / 1568, r = q % 1568;                 // 1568 pairs per image
    int oh = r / 28, pw = r % 28;
    int ow0 = pw * 2;
    int p0 = q * 2;                                 // pixel index of px0
    const uint2* src = g_a1b + n * 12544;
    unsigned* outp = (unsigned*)g_a2b;
    const unsigned* wbase = &sw[jout * 18];

    if (oh > 0 && pw > 0) {                         // interior fast path, static regs
        uint2 c[15];                                // 3 rows x 5 cols window
        int base = (2 * oh - 1) * 112 + (2 * ow0 - 1);
        #pragma unroll
        for (int rr = 0; rr < 3; rr++)
            #pragma unroll
            for (int k = 0; k < 5; k++) c[rr * 5 + k] = src[base + rr * 112 + k];

        unsigned w0v = 0, w1v = 0;
        #pragma unroll 4
        for (int oo = 0; oo < 32; oo++) {
            const unsigned* wp = wbase + oo * 72;
            int P0 = 0, P1 = 0;
            #pragma unroll
            for (int rr = 0; rr < 3; rr++)
                #pragma unroll
                for (int kw = 0; kw < 3; kw++) {
                    int tt = rr * 3 + kw;
                    unsigned ww0 = wp[tt * 2], ww1 = wp[tt * 2 + 1];
                    uint2 l = c[rr * 5 + kw], rt2 = c[rr * 5 + kw + 2];
                    P0 += __popc(l.x ^ ww0) + __popc(l.y ^ ww1);
                    P1 += __popc(rt2.x ^ ww0) + __popc(rt2.y ^ ww1);
                }
            float bb = sb[oo * 4 + jout];
            float y0 = fmaf(a2sq, (float)(576 - 2 * P0), bb);
            float y1 = fmaf(a2sq, (float)(576 - 2 * P1), bb);
            w0v |= (unsigned)(y0 < 0.f) << oo;
            w1v |= (unsigned)(y1 < 0.f) << oo;
        }
        outp[p0 * 4 + jout]     = w0v;
        outp[p0 * 4 + 4 + jout] = w1v;
    } else {                                        // border: one pixel at a time
        #pragma unroll 1
        for (int px = 0; px < 2; px++) {
            int ow = ow0 + px;
            uint2 a[9]; int fl[9];
            #pragma unroll
            for (int kh = 0; kh < 3; kh++)
                #pragma unroll
                for (int kw = 0; kw < 3; kw++) {
                    int tt = kh * 3 + kw;
                    int ih = 2 * oh - 1 + kh, iw = 2 * ow - 1 + kw;
                    bool v = ((unsigned)ih < 112u) && ((unsigned)iw < 112u);
                    a[tt] = v ? src[ih * 112 + iw] : make_uint2(0u, 0u);
                    fl[tt] = v ? 1 : 0;
                }
            int V = 64 * (fl[0] + fl[1] + fl[2] + fl[3] + fl[4] + fl[5] + fl[6] + fl[7] + fl[8]);
            unsigned wv = 0;
            #pragma unroll 1
            for (int oo = 0; oo < 32; oo++) {
                const unsigned* wp = wbase + oo * 72;
                int P = 0;
                #pragma unroll
                for (int tt = 0; tt < 9; tt++) {
                    int d = __popc(a[tt].x ^ wp[tt * 2]) + __popc(a[tt].y ^ wp[tt * 2 + 1]);
                    P += fl[tt] * d;
                }
                float y = fmaf(a2sq, (float)(V - 2 * P), sb[oo * 4 + jout]);
                wv |= (unsigned)(y < 0.f) << oo;
            }
            outp[(p0 + px) * 4 + jout] = wv;
        }
    }
}

// ---------------- layer 3: XNOR conv 128->256, 56->28, fused global-avg-pool sign ----------------
__global__ void __launch_bounds__(256) k_conv3(const float* __restrict__ b3) {
    int n = blockIdx.x >> 5, g = blockIdx.x & 31;   // octet g: channels g*8..g*8+7
    __shared__ unsigned sw[288];
    __shared__ float    sb[8];
    __shared__ int      ssum[8];
    __shared__ float    scorr[8];
    __shared__ float    sh_a;
    for (int i = threadIdx.x; i < 288; i += 256) sw[i] = g_w3b[g * 288 + i];
    if (threadIdx.x < 8) {
        sb[threadIdx.x] = b3[g * 8 + threadIdx.x];
        ssum[threadIdx.x] = 0;
        scorr[threadIdx.x] = 0.f;
    }
    if (threadIdx.x == 0) sh_a = alpha2_of(2);
    __syncthreads();

    float a3sq = sh_a;
    int acc[8];
    #pragma unroll
    for (int c = 0; c < 8; c++) acc[c] = 0;
    const uint4* src = g_a2b + n * 3136;

    for (int pix = threadIdx.x; pix < 784; pix += 256) {
        int oh = pix / 28, ow = pix % 28;
        if (oh > 0 && ow > 0) {                     // interior fast path
            uint4 a[9];
            int base = (2 * oh - 1) * 56 + (2 * ow - 1);
            #pragma unroll
            for (int rr = 0; rr < 3; rr++)
                #pragma unroll
                for (int kw = 0; kw < 3; kw++) a[rr * 3 + kw] = src[base + rr * 56 + kw];
            #pragma unroll
            for (int c = 0; c < 8; c++) {
                const unsigned* wp = &sw[c * 36];
                int P = 0;
                #pragma unroll
                for (int t = 0; t < 9; t++) {
                    uint4 av = a[t];
                    P += __popc(av.x ^ wp[t * 4 + 0]) + __popc(av.y ^ wp[t * 4 + 1])
                       + __popc(av.z ^ wp[t * 4 + 2]) + __popc(av.w ^ wp[t * 4 + 3]);
                }
                int I = 1152 - 2 * P;
                acc[c] += I;
                float y = fmaf(a3sq, (float)I, sb[c]);
                if (fabsf(y) > 1.f) atomicAdd(&scorr[c], (y > 0.f ? 1.f : -1.f) - y);
            }
        } else {                                    // border: gated, static arrays
            uint4 a[9]; int f[9];
            #pragma unroll
            for (int kh = 0; kh < 3; kh++)
                #pragma unroll
                for (int kw = 0; kw < 3; kw++) {
                    int t = kh * 3 + kw;
                    int ih = 2 * oh - 1 + kh, iw = 2 * ow - 1 + kw;
                    bool v = ((unsigned)ih < 56u) && ((unsigned)iw < 56u);
                    a[t] = v ? src[ih * 56 + iw] : make_uint4(0u, 0u, 0u, 0u);
                    f[t] = v ? 1 : 0;
                }
            int V = 128 * (f[0] + f[1] + f[2] + f[3] + f[4] + f[5] + f[6] + f[7] + f[8]);
            #pragma unroll
            for (int c = 0; c < 8; c++) {
                const unsigned* wp = &sw[c * 36];
                int P = 0;
                #pragma unroll
                for (int t = 0; t < 9; t++) {
                    int d = __popc(a[t].x ^ wp[t * 4 + 0]) + __popc(a[t].y ^ wp[t * 4 + 1])
                          + __popc(a[t].z ^ wp[t * 4 + 2]) + __popc(a[t].w ^ wp[t * 4 + 3]);
                    P += f[t] * d;
                }
                int I = V - 2 * P;
                acc[c] += I;
                float y = fmaf(a3sq, (float)I, sb[c]);
                if (fabsf(y) > 1.f) atomicAdd(&scorr[c], (y > 0.f ? 1.f : -1.f) - y);
            }
        }
    }

    #pragma unroll
    for (int c = 0; c < 8; c++) {
        int v = acc[c];
        #pragma unroll
        for (int s = 16; s > 0; s >>= 1) v += __shfl_xor_sync(0xffffffffu, v, s);
        if ((threadIdx.x & 31) == 0) atomicAdd(&ssum[c], v);
    }
    __syncthreads();

    if (threadIdx.x < 8) {
        int c = threadIdx.x;
        float val = fmaf(a3sq, (float)ssum[c], 784.f * sb[c] + scorr[c]);
        unsigned m = __ballot_sync(0xffu, val < 0.f) & 0xffu;
        if (c == 0) g_pb[n * 32 + g] = (unsigned char)m;
    }
}

// ---------------- FC: out[n,k] = af^2 * (256 - 2P) + bf[k] ----------------
__global__ void __launch_bounds__(128) k_fc(const float* __restrict__ bf, float* __restrict__ out) {
    __shared__ float sh_a;
    if (threadIdx.x == 0) sh_a = alpha2_of(3);
    __syncthreads();
    int idx = blockIdx.x * 128 + threadIdx.x;
    if (idx >= 32000) return;
    int n = idx / 1000, k = idx % 1000;
    float afsq = sh_a;
    const uint4* pb = (const uint4*)(g_pb + n * 32);
    const uint4* wb = (const uint4*)(g_wfb + k * 8);
    uint4 p0 = pb[0], p1 = pb[1], w0 = wb[0], w1 = wb[1];
    int P = __popc(p0.x ^ w0.x) + __popc(p0.y ^ w0.y) + __popc(p0.z ^ w0.z) + __popc(p0.w ^ w0.w)
          + __popc(p1.x ^ w1.x) + __popc(p1.y ^ w1.y) + __popc(p1.z ^ w1.z) + __popc(p1.w ^ w1.w);
    out[idx] = fmaf(afsq, (float)(256 - 2 * P), bf[k]);
}

// ---------------- launch ----------------
extern "C" void kernel_launch(void* const* d_in, const int* in_sizes, int n_in,
                              void* d_out, int out_size) {
    const float* x  = (const float*)d_in[0];
    const float* w1 = (const float*)d_in[1];
    const float* b1 = (const float*)d_in[2];
    const float* w2 = (const float*)d_in[3];
    const float* b2 = (const float*)d_in[4];
    const float* w3 = (const float*)d_in[5];
    const float* b3 = (const float*)d_in[6];
    const float* wf = (const float*)d_in[7];
    const float* bf = (const float*)d_in[8];
    float* out = (float*)d_out;

    k_prep<<<142, 256>>>(w1, w2, w3, wf);
    k_conv1<<<3136, 128>>>(x, b1);
    k_conv2<<<1568, 128>>>(b2);
    k_conv3<<<1024, 256>>>(b3);
    k_fc<<<250, 128>>>(bf, out);
}

// round 4
// speedup vs baseline: 2.2059x; 1.2009x over previous
#include <cuda_runtime.h>
#include <stdint.h>

// ---------------- scratch (static __device__, no allocs) ----------------
__device__ float    g_partial[64];
__device__ unsigned g_w1b[64];                     // 27 bits: c*9 + kh*3 + kw
__device__ unsigned g_w2b[128 * 18];               // reordered: [oo][jout][t][jin]
__device__ unsigned g_w3b[256 * 36];               // [o][t][jw]
__device__ __align__(16) unsigned g_wfb[1000 * 8]; // [k][j] 256 bits
__device__ unsigned g_xb[32 * 3 * 224 * 7];        // x sign bits: [n][ch][row][7 words]
__device__ uint2    g_a1b[32 * 112 * 112];         // layer1 sign bits, 64 ch
__device__ uint4    g_a2b[32 * 56 * 56];           // layer2 sign bits, 128 ch
__device__ __align__(16) unsigned char g_pb[32 * 32]; // pooled sign bits, byte = 8 ch

// alpha^2 for layer t, recomputed deterministically from fixed-order partials
__device__ __forceinline__ float alpha2_of(int t) {
    float s = 0.f;
    #pragma unroll
    for (int j = 0; j < 16; j++) s += g_partial[t * 16 + j];
    const float Ns[4] = {1728.f, 73728.f, 294912.f, 256000.f};
    float a = s / Ns[t];
    return a * a;
}

// ---------------- prep: alpha partials + all weight bit-packing, one launch ----------------
__global__ void __launch_bounds__(256) k_prep(const float* __restrict__ w1,
                                              const float* __restrict__ w2,
                                              const float* __restrict__ w3,
                                              const float* __restrict__ wf) {
    int b = blockIdx.x, tid = threadIdx.x;
    if (b < 64) {                                   // abs-sum partials
        int t = b >> 4, j = b & 15;
        const float* p; int N;
        if      (t == 0) { p = w1; N = 1728;   }
        else if (t == 1) { p = w2; N = 73728;  }
        else if (t == 2) { p = w3; N = 294912; }
        else             { p = wf; N = 256000; }
        float s = 0.f;
        for (int i = j * 256 + tid; i < N; i += 16 * 256) s += fabsf(p[i]);
        __shared__ float sh[256];
        sh[tid] = s; __syncthreads();
        for (int k = 128; k > 0; k >>= 1) {
            if (tid < k) sh[tid] += sh[tid + k];
            __syncthreads();
        }
        if (tid == 0) g_partial[b] = sh[0];
    } else if (b == 64) {                           // pack w1
        if (tid < 64) {
            int o = tid;
            unsigned bb = 0;
            for (int t = 0; t < 27; t++) if (w1[o * 27 + t] < 0.f) bb |= 1u << t;
            g_w1b[o] = bb;
        }
    } else if (b < 74) {                            // pack w2: 2304 ids, reordered dst
        int id = (b - 65) * 256 + tid;
        if (id < 128 * 18) {
            int o = id / 18, r = id % 18, t = r >> 1, j = r & 1;
            unsigned bb = 0;
            for (int c = 0; c < 32; c++)
                if (w2[o * 576 + (j * 32 + c) * 9 + t] < 0.f) bb |= 1u << c;
            g_w2b[(o & 31) * 72 + (o >> 5) * 18 + t * 2 + j] = bb;
        }
    } else if (b < 110) {                           // pack w3: 9216 ids
        int id = (b - 74) * 256 + tid;
        if (id < 256 * 36) {
            int o = id / 36, r = id % 36, t = r >> 2, j = r & 3;
            unsigned bb = 0;
            for (int c = 0; c < 32; c++)
                if (w3[o * 1152 + (j * 32 + c) * 9 + t] < 0.f) bb |= 1u << c;
            g_w3b[o * 36 + t * 4 + j] = bb;
        }
    } else {                                        // pack wf: 8000 ids
        int id = (b - 110) * 256 + tid;
        if (id < 1000 * 8) {
            int k = id / 8, j = id % 8;
            unsigned bb = 0;
            for (int c = 0; c < 32; c++)
                if (wf[k * 256 + j * 32 + c] < 0.f) bb |= 1u << c;
            g_wfb[k * 8 + j] = bb;
        }
    }
}

// ---------------- pack x sign bits: 150528 words, 32 floats per word ----------------
__global__ void __launch_bounds__(256) k_packx(const float4* __restrict__ x) {
    int w = blockIdx.x * 256 + threadIdx.x;         // 588*256 = 150528 exact
    const float4* p = x + (size_t)w * 8;
    unsigned b = 0;
    #pragma unroll
    for (int i = 0; i < 8; i++) {
        float4 v = p[i];
        b |= (unsigned)(v.x < 0.f) << (4 * i)
           | (unsigned)(v.y < 0.f) << (4 * i + 1)
           | (unsigned)(v.z < 0.f) << (4 * i + 2)
           | (unsigned)(v.w < 0.f) << (4 * i + 3);
    }
    g_xb[w] = b;
}

// ---------------- layer 1 from bits: 8 output px per thread ----------------
__global__ void __launch_bounds__(128) k_conv1b(const float* __restrict__ b1) {
    __shared__ unsigned sw[64];
    __shared__ float    sb[64];
    __shared__ float    sh_a;
    if (threadIdx.x < 64) { sw[threadIdx.x] = g_w1b[threadIdx.x]; sb[threadIdx.x] = b1[threadIdx.x]; }
    if (threadIdx.x == 0) sh_a = alpha2_of(0);
    __syncthreads();

    int t = blockIdx.x * 128 + threadIdx.x;         // 50176 exact
    int n = t / 1568, r = t % 1568;                 // 1568 = 112 rows * 14 groups
    int oh = r / 14, g = r % 14;
    int ow0 = g * 8;
    float a1sq = sh_a;

    int cb = 2 * ow0 - 1;                           // leftmost input col (may be -1)
    int a = cb >> 5;                                // arithmetic shift: -1 when ow0==0
    int shft = cb - (a << 5);                       // 31 when a==-1

    unsigned long long W[9];
    #pragma unroll
    for (int ch = 0; ch < 3; ch++)
        #pragma unroll
        for (int kh = 0; kh < 3; kh++) {
            int ih = 2 * oh - 1 + kh;
            unsigned w0 = 0, w1 = 0;
            if (ih >= 0) {                          // ih max 223, always valid high side
                int rowbase = ((n * 3 + ch) * 224 + ih) * 7;
                if (a >= 0)     w0 = g_xb[rowbase + a];
                if (a + 1 <= 6) w1 = g_xb[rowbase + a + 1];
            }
            W[ch * 3 + kh] = ((unsigned long long)w1 << 32) | w0;
        }

    uint2* outp = g_a1b + (n * 112 + oh) * 112 + ow0;
    #pragma unroll
    for (int k = 0; k < 8; k++) {
        unsigned xb = 0;
        #pragma unroll
        for (int ch = 0; ch < 3; ch++)
            #pragma unroll
            for (int kh = 0; kh < 3; kh++) {
                unsigned bits = (unsigned)(W[ch * 3 + kh] >> (shft + 2 * k)) & 7u;
                xb |= bits << (ch * 9 + kh * 3);
            }
        unsigned mask = 0x7FFFFFFu;
        if (oh == 0) mask &= ~0x1C0E07u;            // kh==0 taps for all 3 ch
        if (ow0 == 0 && k == 0) mask &= ~0x1249249u;// kw==0 taps for all 3 ch
        int V = __popc(mask);

        unsigned wo0 = 0, wo1 = 0;
        #pragma unroll 4
        for (int o = 0; o < 32; o++) {
            int p = __popc((xb ^ sw[o]) & mask);    // single LOP3 + POPC
            float y = fmaf(a1sq, (float)(V - 2 * p), sb[o]);
            wo0 |= (unsigned)(y < 0.f) << o;
        }
        #pragma unroll 4
        for (int o = 0; o < 32; o++) {
            int p = __popc((xb ^ sw[32 + o]) & mask);
            float y = fmaf(a1sq, (float)(V - 2 * p), sb[32 + o]);
            wo1 |= (unsigned)(y < 0.f) << o;
        }
        outp[k] = make_uint2(wo0, wo1);
    }
}

// ---------------- layer 2: XNOR conv 64->128, stride 2, 112->56 ----------------
// thread = (pixel-pair q, output-channel word jout). 200704 threads.
__global__ void __launch_bounds__(128) k_conv2(const float* __restrict__ b2) {
    __shared__ unsigned sw[2304];                   // [oo][jout][t][jin]
    __shared__ float    sb[128];                    // [oo][jout]
    __shared__ float    sh_a;
    for (int i = threadIdx.x; i < 2304; i += 128) sw[i] = g_w2b[i];
    if (threadIdx.x < 128) sb[(threadIdx.x & 31) * 4 + (threadIdx.x >> 5)] = b2[threadIdx.x];
    if (threadIdx.x == 0) sh_a = alpha2_of(1);
    __syncthreads();
    float a2sq = sh_a;

    int t = blockIdx.x * 128 + threadIdx.x;         // 200704 exact
    int jout = t & 3, q = t >> 2;                   // q in [0, 50176)
    int n = q / 1568, r = q % 1568;                 // 1568 pairs per image
    int oh = r / 28, pw = r % 28;
    int ow0 = pw * 2;
    int p0 = q * 2;                                 // pixel index of px0
    const uint2* src = g_a1b + n * 12544;
    unsigned* outp = (unsigned*)g_a2b;
    const unsigned* wbase = &sw[jout * 18];

    if (oh > 0 && pw > 0) {                         // interior fast path, static regs
        uint2 c[15];                                // 3 rows x 5 cols window
        int base = (2 * oh - 1) * 112 + (2 * ow0 - 1);
        #pragma unroll
        for (int rr = 0; rr < 3; rr++)
            #pragma unroll
            for (int k = 0; k < 5; k++) c[rr * 5 + k] = src[base + rr * 112 + k];

        unsigned w0v = 0, w1v = 0;
        #pragma unroll 4
        for (int oo = 0; oo < 32; oo++) {
            const unsigned* wp = wbase + oo * 72;
            int P0 = 0, P1 = 0;
            #pragma unroll
            for (int rr = 0; rr < 3; rr++)
                #pragma unroll
                for (int kw = 0; kw < 3; kw++) {
                    int tt = rr * 3 + kw;
                    unsigned ww0 = wp[tt * 2], ww1 = wp[tt * 2 + 1];
                    uint2 l = c[rr * 5 + kw], rt2 = c[rr * 5 + kw + 2];
                    P0 += __popc(l.x ^ ww0) + __popc(l.y ^ ww1);
                    P1 += __popc(rt2.x ^ ww0) + __popc(rt2.y ^ ww1);
                }
            float bb = sb[oo * 4 + jout];
            float y0 = fmaf(a2sq, (float)(576 - 2 * P0), bb);
            float y1 = fmaf(a2sq, (float)(576 - 2 * P1), bb);
            w0v |= (unsigned)(y0 < 0.f) << oo;
            w1v |= (unsigned)(y1 < 0.f) << oo;
        }
        outp[p0 * 4 + jout]     = w0v;
        outp[p0 * 4 + 4 + jout] = w1v;
    } else {                                        // border: one pixel at a time
        #pragma unroll 1
        for (int px = 0; px < 2; px++) {
            int ow = ow0 + px;
            uint2 a[9]; int fl[9];
            #pragma unroll
            for (int kh = 0; kh < 3; kh++)
                #pragma unroll
                for (int kw = 0; kw < 3; kw++) {
                    int tt = kh * 3 + kw;
                    int ih = 2 * oh - 1 + kh, iw = 2 * ow - 1 + kw;
                    bool v = ((unsigned)ih < 112u) && ((unsigned)iw < 112u);
                    a[tt] = v ? src[ih * 112 + iw] : make_uint2(0u, 0u);
                    fl[tt] = v ? 1 : 0;
                }
            int V = 64 * (fl[0] + fl[1] + fl[2] + fl[3] + fl[4] + fl[5] + fl[6] + fl[7] + fl[8]);
            unsigned wv = 0;
            #pragma unroll 1
            for (int oo = 0; oo < 32; oo++) {
                const unsigned* wp = wbase + oo * 72;
                int P = 0;
                #pragma unroll
                for (int tt = 0; tt < 9; tt++) {
                    int d = __popc(a[tt].x ^ wp[tt * 2]) + __popc(a[tt].y ^ wp[tt * 2 + 1]);
                    P += fl[tt] * d;
                }
                float y = fmaf(a2sq, (float)(V - 2 * P), sb[oo * 4 + jout]);
                wv |= (unsigned)(y < 0.f) << oo;
            }
            outp[(p0 + px) * 4 + jout] = wv;
        }
    }
}

// ---------------- layer 3: tap-outer XNOR conv 128->256 + fused pooled sign ----------------
__global__ void __launch_bounds__(256, 5) k_conv3(const float* __restrict__ b3) {
    int n = blockIdx.x >> 5, g = blockIdx.x & 31;   // octet g: channels g*8..g*8+7
    __shared__ unsigned sw[288];
    __shared__ float    sb[8];
    __shared__ int      ssum[8];
    __shared__ float    scorr[8];
    __shared__ float    sh_a;
    __shared__ int      sR[8], sC[8], sT0[8];       // border weight-popcount corrections
    for (int i = threadIdx.x; i < 288; i += 256) sw[i] = g_w3b[g * 288 + i];
    if (threadIdx.x < 8) {
        sb[threadIdx.x] = b3[g * 8 + threadIdx.x];
        ssum[threadIdx.x] = 0;
        scorr[threadIdx.x] = 0.f;
    }
    if (threadIdx.x == 0) sh_a = alpha2_of(2);
    __syncthreads();
    if (threadIdx.x < 8) {
        int c = threadIdx.x;
        int rr = 0, cc = 0;
        #pragma unroll
        for (int t = 0; t < 3; t++)                 // row 0 taps: 0,1,2
            rr += __popc(sw[c*36+t*4]) + __popc(sw[c*36+t*4+1]) + __popc(sw[c*36+t*4+2]) + __popc(sw[c*36+t*4+3]);
        #pragma unroll
        for (int kk = 0; kk < 3; kk++) {            // col 0 taps: 0,3,6
            int t = kk * 3;
            cc += __popc(sw[c*36+t*4]) + __popc(sw[c*36+t*4+1]) + __popc(sw[c*36+t*4+2]) + __popc(sw[c*36+t*4+3]);
        }
        sR[c] = rr; sC[c] = cc;
        sT0[c] = __popc(sw[c*36]) + __popc(sw[c*36+1]) + __popc(sw[c*36+2]) + __popc(sw[c*36+3]);
    }
    __syncthreads();

    float a3sq = sh_a;
    int acc[8];
    #pragma unroll
    for (int c = 0; c < 8; c++) acc[c] = 0;
    const uint4* src = g_a2b + n * 3136;

    for (int pix = threadIdx.x; pix < 784; pix += 256) {
        int oh = pix / 28, ow = pix % 28;
        int base = (2 * oh - 1) * 56 + (2 * ow - 1);
        int P[8];
        #pragma unroll
        for (int c = 0; c < 8; c++) P[c] = 0;
        #pragma unroll
        for (int t = 0; t < 9; t++) {
            int kh = t / 3, kw = t % 3;
            uint4 av = make_uint4(0u, 0u, 0u, 0u);
            if ((kh | oh) && (kw | ow))             // predicated LDG; off => av stays 0
                av = src[base + kh * 56 + kw];
            #pragma unroll
            for (int c = 0; c < 8; c++) {
                const unsigned* wp = &sw[c * 36 + t * 4];
                P[c] += __popc(av.x ^ wp[0]) + __popc(av.y ^ wp[1])
                      + __popc(av.z ^ wp[2]) + __popc(av.w ^ wp[3]);
            }
        }
        int V = 1152;
        if (oh == 0 || ow == 0) {                   // remove popc(w) from zeroed taps
            int rv = oh ? 3 : 2, cv = ow ? 3 : 2;
            V = 128 * rv * cv;
            #pragma unroll
            for (int c = 0; c < 8; c++) {
                int adj = 0;
                if (oh == 0) adj += sR[c];
                if (ow == 0) adj += sC[c];
                if (oh == 0 && ow == 0) adj -= sT0[c];
                P[c] -= adj;
            }
        }
        #pragma unroll
        for (int c = 0; c < 8; c++) {
            int I = V - 2 * P[c];
            acc[c] += I;
            float y = fmaf(a3sq, (float)I, sb[c]);
            if (fabsf(y) > 1.f) atomicAdd(&scorr[c], (y > 0.f ? 1.f : -1.f) - y);
        }
    }

    #pragma unroll
    for (int c = 0; c < 8; c++) {
        int v = acc[c];
        #pragma unroll
        for (int s = 16; s > 0; s >>= 1) v += __shfl_xor_sync(0xffffffffu, v, s);
        if ((threadIdx.x & 31) == 0) atomicAdd(&ssum[c], v);
    }
    __syncthreads();

    if (threadIdx.x < 8) {
        int c = threadIdx.x;
        float val = fmaf(a3sq, (float)ssum[c], 784.f * sb[c] + scorr[c]);
        unsigned m = __ballot_sync(0xffu, val < 0.f) & 0xffu;
        if (c == 0) g_pb[n * 32 + g] = (unsigned char)m;
    }
}

// ---------------- FC: out[n,k] = af^2 * (256 - 2P) + bf[k] ----------------
__global__ void __launch_bounds__(128) k_fc(const float* __restrict__ bf, float* __restrict__ out) {
    __shared__ float sh_a;
    if (threadIdx.x == 0) sh_a = alpha2_of(3);
    __syncthreads();
    int idx = blockIdx.x * 128 + threadIdx.x;
    if (idx >= 32000) return;
    int n = idx / 1000, k = idx % 1000;
    float afsq = sh_a;
    const uint4* pb = (const uint4*)(g_pb + n * 32);
    const uint4* wb = (const uint4*)(g_wfb + k * 8);
    uint4 p0 = pb[0], p1 = pb[1], w0 = wb[0], w1 = wb[1];
    int P = __popc(p0.x ^ w0.x) + __popc(p0.y ^ w0.y) + __popc(p0.z ^ w0.z) + __popc(p0.w ^ w0.w)
          + __popc(p1.x ^ w1.x) + __popc(p1.y ^ w1.y) + __popc(p1.z ^ w1.z) + __popc(p1.w ^ w1.w);
    out[idx] = fmaf(afsq, (float)(256 - 2 * P), bf[k]);
}

// ---------------- launch ----------------
extern "C" void kernel_launch(void* const* d_in, const int* in_sizes, int n_in,
                              void* d_out, int out_size) {
    const float* x  = (const float*)d_in[0];
    const float* w1 = (const float*)d_in[1];
    const float* b1 = (const float*)d_in[2];
    const float* w2 = (const float*)d_in[3];
    const float* b2 = (const float*)d_in[4];
    const float* w3 = (const float*)d_in[5];
    const float* b3 = (const float*)d_in[6];
    const float* wf = (const float*)d_in[7];
    const float* bf = (const float*)d_in[8];
    float* out = (float*)d_out;

    k_prep<<<142, 256>>>(w1, w2, w3, wf);
    k_packx<<<588, 256>>>((const float4*)x);
    k_conv1b<<<392, 128>>>(b1);
    k_conv2<<<1568, 128>>>(b2);
    k_conv3<<<1024, 256>>>(b3);
    k_fc<<<250, 128>>>(bf, out);
}

// round 5
// speedup vs baseline: 2.8212x; 1.2789x over previous
#include <cuda_runtime.h>
#include <stdint.h>

// ---------------- scratch (static __device__, no allocs) ----------------
__device__ float    g_partial[64];
__device__ unsigned g_w1b[64];                     // 27 bits: c*9 + kh*3 + kw
__device__ unsigned g_w2b[128 * 18];               // [jout][tap][jin][oo]
__device__ unsigned g_w3b[256 * 36];               // [o][t][jw]
__device__ __align__(16) unsigned g_wfb[1000 * 8]; // [k][j] 256 bits
__device__ unsigned g_xb[32 * 3 * 224 * 7];        // x sign bits: [n][ch][row][7 words]
__device__ uint2    g_a1b[32 * 112 * 112];         // layer1 sign bits, 64 ch
__device__ uint4    g_a2b[32 * 56 * 56];           // layer2 sign bits, 128 ch
__device__ __align__(16) unsigned char g_pb[32 * 32]; // pooled sign bits, byte = 8 ch

// alpha^2 for layer t, recomputed deterministically from fixed-order partials
__device__ __forceinline__ float alpha2_of(int t) {
    float s = 0.f;
    #pragma unroll
    for (int j = 0; j < 16; j++) s += g_partial[t * 16 + j];
    const float Ns[4] = {1728.f, 73728.f, 294912.f, 256000.f};
    float a = s / Ns[t];
    return a * a;
}

// ---------------- prep: alpha partials + all weight bit-packing, one launch ----------------
__global__ void __launch_bounds__(256) k_prep(const float* __restrict__ w1,
                                              const float* __restrict__ w2,
                                              const float* __restrict__ w3,
                                              const float* __restrict__ wf) {
    int b = blockIdx.x, tid = threadIdx.x;
    if (b < 64) {                                   // abs-sum partials
        int t = b >> 4, j = b & 15;
        const float* p; int N;
        if      (t == 0) { p = w1; N = 1728;   }
        else if (t == 1) { p = w2; N = 73728;  }
        else if (t == 2) { p = w3; N = 294912; }
        else             { p = wf; N = 256000; }
        float s = 0.f;
        for (int i = j * 256 + tid; i < N; i += 16 * 256) s += fabsf(p[i]);
        __shared__ float sh[256];
        sh[tid] = s; __syncthreads();
        for (int k = 128; k > 0; k >>= 1) {
            if (tid < k) sh[tid] += sh[tid + k];
            __syncthreads();
        }
        if (tid == 0) g_partial[b] = sh[0];
    } else if (b == 64) {                           // pack w1
        if (tid < 64) {
            int o = tid;
            unsigned bb = 0;
            for (int t = 0; t < 27; t++) if (w1[o * 27 + t] < 0.f) bb |= 1u << t;
            g_w1b[o] = bb;
        }
    } else if (b < 74) {                            // pack w2: 2304 ids -> [jout][t][jin][oo]
        int id = (b - 65) * 256 + tid;
        if (id < 128 * 18) {
            int o = id / 18, r = id % 18, t = r >> 1, j = r & 1;
            unsigned bb = 0;
            for (int c = 0; c < 32; c++)
                if (w2[o * 576 + (j * 32 + c) * 9 + t] < 0.f) bb |= 1u << c;
            g_w2b[((o >> 5) * 18 + t * 2 + j) * 32 + (o & 31)] = bb;
        }
    } else if (b < 110) {                           // pack w3: 9216 ids
        int id = (b - 74) * 256 + tid;
        if (id < 256 * 36) {
            int o = id / 36, r = id % 36, t = r >> 2, j = r & 3;
            unsigned bb = 0;
            for (int c = 0; c < 32; c++)
                if (w3[o * 1152 + (j * 32 + c) * 9 + t] < 0.f) bb |= 1u << c;
            g_w3b[o * 36 + t * 4 + j] = bb;
        }
    } else {                                        // pack wf: 8000 ids
        int id = (b - 110) * 256 + tid;
        if (id < 1000 * 8) {
            int k = id / 8, j = id % 8;
            unsigned bb = 0;
            for (int c = 0; c < 32; c++)
                if (wf[k * 256 + j * 32 + c] < 0.f) bb |= 1u << c;
            g_wfb[k * 8 + j] = bb;
        }
    }
}

// ---------------- pack x sign bits: 150528 words, 32 floats per word ----------------
__global__ void __launch_bounds__(256) k_packx(const float4* __restrict__ x) {
    int w = blockIdx.x * 256 + threadIdx.x;         // 588*256 = 150528 exact
    const float4* p = x + (size_t)w * 8;
    unsigned b = 0;
    #pragma unroll
    for (int i = 0; i < 8; i++) {
        float4 v = p[i];
        b |= (unsigned)(v.x < 0.f) << (4 * i)
           | (unsigned)(v.y < 0.f) << (4 * i + 1)
           | (unsigned)(v.z < 0.f) << (4 * i + 2)
           | (unsigned)(v.w < 0.f) << (4 * i + 3);
    }
    g_xb[w] = b;
}

// ---------------- layer 1 from bits: 4 output px per thread ----------------
__global__ void __launch_bounds__(128) k_conv1b(const float* __restrict__ b1) {
    __shared__ unsigned sw[64];
    __shared__ float    sb[64];
    __shared__ float    sh_a;
    if (threadIdx.x < 64) { sw[threadIdx.x] = g_w1b[threadIdx.x]; sb[threadIdx.x] = b1[threadIdx.x]; }
    if (threadIdx.x == 0) sh_a = alpha2_of(0);
    __syncthreads();

    int t = blockIdx.x * 128 + threadIdx.x;         // 100352 exact
    int n = t / 3136, r = t % 3136;                 // 3136 = 112 rows * 28 groups
    int oh = r / 28, g = r % 28;
    int ow0 = g * 4;
    float a1sq = sh_a;

    int cb = 2 * ow0 - 1;                           // leftmost input col (may be -1)
    int a = cb >> 5;                                // arithmetic shift: -1 when ow0==0
    int shft = cb - (a << 5);                       // 31 when a==-1

    unsigned long long W[9];
    #pragma unroll
    for (int ch = 0; ch < 3; ch++)
        #pragma unroll
        for (int kh = 0; kh < 3; kh++) {
            int ih = 2 * oh - 1 + kh;
            unsigned w0 = 0, w1 = 0;
            if (ih >= 0) {                          // ih max 223, always valid high side
                int rowbase = ((n * 3 + ch) * 224 + ih) * 7;
                if (a >= 0)     w0 = g_xb[rowbase + a];
                if (a + 1 <= 6) w1 = g_xb[rowbase + a + 1];
            }
            W[ch * 3 + kh] = ((unsigned long long)w1 << 32) | w0;
        }

    uint2* outp = g_a1b + (n * 112 + oh) * 112 + ow0;
    #pragma unroll
    for (int k = 0; k < 4; k++) {
        unsigned xb = 0;
        #pragma unroll
        for (int ch = 0; ch < 3; ch++)
            #pragma unroll
            for (int kh = 0; kh < 3; kh++) {
                unsigned bits = (unsigned)(W[ch * 3 + kh] >> (shft + 2 * k)) & 7u;
                xb |= bits << (ch * 9 + kh * 3);
            }
        unsigned mask = 0x7FFFFFFu;
        if (oh == 0) mask &= ~0x1C0E07u;            // kh==0 taps for all 3 ch
        if (ow0 == 0 && k == 0) mask &= ~0x1249249u;// kw==0 taps for all 3 ch
        int V = __popc(mask);

        unsigned wo0 = 0, wo1 = 0;
        #pragma unroll 4
        for (int o = 0; o < 32; o++) {
            int p = __popc((xb ^ sw[o]) & mask);    // single LOP3 + POPC
            float y = fmaf(a1sq, (float)(V - 2 * p), sb[o]);
            wo0 |= (unsigned)(y < 0.f) << o;
        }
        #pragma unroll 4
        for (int o = 0; o < 32; o++) {
            int p = __popc((xb ^ sw[32 + o]) & mask);
            float y = fmaf(a1sq, (float)(V - 2 * p), sb[32 + o]);
            wo1 |= (unsigned)(y < 0.f) << o;
        }
        outp[k] = make_uint2(wo0, wo1);
    }
}

// ---------------- layer 2: ballot scheme. lane=oo, warp=(jout, px-strip) ----------------
// block = one (n, oh) output row. 8 warps: jout = w&3, half = w>>2 (28 px each).
__global__ void __launch_bounds__(256) k_conv2(const float* __restrict__ b2) {
    __shared__ uint2 srow[3][114];                  // input row tile, zero-padded
    __shared__ float sh_a;
    int blk = blockIdx.x;                           // 1792 = 32*56
    int n = blk / 56, oh = blk % 56;
    int tid = threadIdx.x, lane = tid & 31, w = tid >> 5;
    int jout = w & 3, half = w >> 2;

    if (tid == 0) sh_a = alpha2_of(1);
    for (int i = tid; i < 342; i += 256) {          // 3*114 entries
        int kh = i / 114, col = i % 114;
        int ih = 2 * oh - 1 + kh, iw = col - 1;
        uint2 v = make_uint2(0u, 0u);
        if ((unsigned)ih < 112u && (unsigned)iw < 112u)
            v = g_a1b[(n * 112 + ih) * 112 + iw];
        srow[kh][col] = v;
    }

    // per-lane weights for channel jout*32+lane: 18 words, coalesced
    unsigned wreg[18];
    #pragma unroll
    for (int i = 0; i < 18; i++) wreg[i] = g_w2b[(jout * 18 + i) * 32 + lane];
    float bb = b2[jout * 32 + lane];

    // border popcount corrections (per-lane, from registers)
    int pR = 0, pC = 0;
    #pragma unroll
    for (int t = 0; t < 3; t++) pR += __popc(wreg[t * 2]) + __popc(wreg[t * 2 + 1]);
    #pragma unroll
    for (int k = 0; k < 3; k++) pC += __popc(wreg[k * 6]) + __popc(wreg[k * 6 + 1]);
    int pT0 = __popc(wreg[0]) + __popc(wreg[1]);
    __syncthreads();

    float a2sq = sh_a;
    int rowflag = (oh == 0);
    int rAdj = rowflag ? pR : 0;
    int Vrow = rowflag ? 2 : 3;

    unsigned* outp = (unsigned*)g_a2b + (size_t)(n * 56 + oh) * 56 * 4 + jout;
    #pragma unroll 2
    for (int i = 0; i < 28; i++) {
        int ow = half * 28 + i;
        int b0 = 2 * ow;                            // smem col of iw = 2ow-1
        int P = 0;
        #pragma unroll
        for (int kh = 0; kh < 3; kh++)
            #pragma unroll
            for (int kw = 0; kw < 3; kw++) {
                uint2 av = srow[kh][b0 + kw];       // warp-uniform -> broadcast
                int t = kh * 3 + kw;
                P += __popc(av.x ^ wreg[t * 2]) + __popc(av.y ^ wreg[t * 2 + 1]);
            }
        int adj = rAdj;
        int V = 64 * Vrow * 3;
        if (ow == 0) { adj += pC - (rowflag ? pT0 : 0); V = 64 * Vrow * 2; }
        float y = fmaf(a2sq, (float)(V - 2 * (P - adj)), bb);
        unsigned word = __ballot_sync(0xffffffffu, y < 0.f);
        if (lane == 0) outp[ow * 4] = word;
    }
}

// ---------------- layer 3: tap-outer XNOR conv 128->256 + fused pooled sign ----------------
__global__ void __launch_bounds__(256, 5) k_conv3(const float* __restrict__ b3) {
    int n = blockIdx.x >> 5, g = blockIdx.x & 31;   // octet g: channels g*8..g*8+7
    __shared__ unsigned sw[288];
    __shared__ float    sb[8];
    __shared__ int      ssum[8];
    __shared__ float    scorr[8];
    __shared__ float    sh_a;
    __shared__ int      sR[8], sC[8], sT0[8];       // border weight-popcount corrections
    for (int i = threadIdx.x; i < 288; i += 256) sw[i] = g_w3b[g * 288 + i];
    if (threadIdx.x < 8) {
        sb[threadIdx.x] = b3[g * 8 + threadIdx.x];
        ssum[threadIdx.x] = 0;
        scorr[threadIdx.x] = 0.f;
    }
    if (threadIdx.x == 0) sh_a = alpha2_of(2);
    __syncthreads();
    if (threadIdx.x < 8) {
        int c = threadIdx.x;
        int rr = 0, cc = 0;
        #pragma unroll
        for (int t = 0; t < 3; t++)                 // row 0 taps: 0,1,2
            rr += __popc(sw[c*36+t*4]) + __popc(sw[c*36+t*4+1]) + __popc(sw[c*36+t*4+2]) + __popc(sw[c*36+t*4+3]);
        #pragma unroll
        for (int kk = 0; kk < 3; kk++) {            // col 0 taps: 0,3,6
            int t = kk * 3;
            cc += __popc(sw[c*36+t*4]) + __popc(sw[c*36+t*4+1]) + __popc(sw[c*36+t*4+2]) + __popc(sw[c*36+t*4+3]);
        }
        sR[c] = rr; sC[c] = cc;
        sT0[c] = __popc(sw[c*36]) + __popc(sw[c*36+1]) + __popc(sw[c*36+2]) + __popc(sw[c*36+3]);
    }
    __syncthreads();

    float a3sq = sh_a;
    int acc[8];
    #pragma unroll
    for (int c = 0; c < 8; c++) acc[c] = 0;
    const uint4* src = g_a2b + n * 3136;

    for (int pix = threadIdx.x; pix < 784; pix += 256) {
        int oh = pix / 28, ow = pix % 28;
        int base = (2 * oh - 1) * 56 + (2 * ow - 1);
        int P[8];
        #pragma unroll
        for (int c = 0; c < 8; c++) P[c] = 0;
        #pragma unroll
        for (int t = 0; t < 9; t++) {
            int kh = t / 3, kw = t % 3;
            uint4 av = make_uint4(0u, 0u, 0u, 0u);
            if ((kh | oh) && (kw | ow))             // predicated LDG; off => av stays 0
                av = src[base + kh * 56 + kw];
            #pragma unroll
            for (int c = 0; c < 8; c++) {
                const unsigned* wp = &sw[c * 36 + t * 4];
                P[c] += __popc(av.x ^ wp[0]) + __popc(av.y ^ wp[1])
                      + __popc(av.z ^ wp[2]) + __popc(av.w ^ wp[3]);
            }
        }
        int V = 1152;
        if (oh == 0 || ow == 0) {                   // remove popc(w) from zeroed taps
            int rv = oh ? 3 : 2, cv = ow ? 3 : 2;
            V = 128 * rv * cv;
            #pragma unroll
            for (int c = 0; c < 8; c++) {
                int adj = 0;
                if (oh == 0) adj += sR[c];
                if (ow == 0) adj += sC[c];
                if (oh == 0 && ow == 0) adj -= sT0[c];
                P[c] -= adj;
            }
        }
        #pragma unroll
        for (int c = 0; c < 8; c++) {
            int I = V - 2 * P[c];
            acc[c] += I;
            float y = fmaf(a3sq, (float)I, sb[c]);
            if (fabsf(y) > 1.f) atomicAdd(&scorr[c], (y > 0.f ? 1.f : -1.f) - y);
        }
    }

    #pragma unroll
    for (int c = 0; c < 8; c++) {
        int v = acc[c];
        #pragma unroll
        for (int s = 16; s > 0; s >>= 1) v += __shfl_xor_sync(0xffffffffu, v, s);
        if ((threadIdx.x & 31) == 0) atomicAdd(&ssum[c], v);
    }
    __syncthreads();

    if (threadIdx.x < 8) {
        int c = threadIdx.x;
        float val = fmaf(a3sq, (float)ssum[c], 784.f * sb[c] + scorr[c]);
        unsigned m = __ballot_sync(0xffu, val < 0.f) & 0xffu;
        if (c == 0) g_pb[n * 32 + g] = (unsigned char)m;
    }
}

// ---------------- FC: out[n,k] = af^2 * (256 - 2P) + bf[k] ----------------
__global__ void __launch_bounds__(128) k_fc(const float* __restrict__ bf, float* __restrict__ out) {
    __shared__ float sh_a;
    if (threadIdx.x == 0) sh_a = alpha2_of(3);
    __syncthreads();
    int idx = blockIdx.x * 128 + threadIdx.x;
    if (idx >= 32000) return;
    int n = idx / 1000, k = idx % 1000;
    float afsq = sh_a;
    const uint4* pb = (const uint4*)(g_pb + n * 32);
    const uint4* wb = (const uint4*)(g_wfb + k * 8);
    uint4 p0 = pb[0], p1 = pb[1], w0 = wb[0], w1 = wb[1];
    int P = __popc(p0.x ^ w0.x) + __popc(p0.y ^ w0.y) + __popc(p0.z ^ w0.z) + __popc(p0.w ^ w0.w)
          + __popc(p1.x ^ w1.x) + __popc(p1.y ^ w1.y) + __popc(p1.z ^ w1.z) + __popc(p1.w ^ w1.w);
    out[idx] = fmaf(afsq, (float)(256 - 2 * P), bf[k]);
}

// ---------------- launch ----------------
extern "C" void kernel_launch(void* const* d_in, const int* in_sizes, int n_in,
                              void* d_out, int out_size) {
    const float* x  = (const float*)d_in[0];
    const float* w1 = (const float*)d_in[1];
    const float* b1 = (const float*)d_in[2];
    const float* w2 = (const float*)d_in[3];
    const float* b2 = (const float*)d_in[4];
    const float* w3 = (const float*)d_in[5];
    const float* b3 = (const float*)d_in[6];
    const float* wf = (const float*)d_in[7];
    const float* bf = (const float*)d_in[8];
    float* out = (float*)d_out;

    k_prep<<<142, 256>>>(w1, w2, w3, wf);
    k_packx<<<588, 256>>>((const float4*)x);
    k_conv1b<<<784, 128>>>(b1);
    k_conv2<<<1792, 256>>>(b2);
    k_conv3<<<1024, 256>>>(b3);
    k_fc<<<250, 128>>>(bf, out);
}